// round 1
// baseline (speedup 1.0000x reference)
#include <cuda_runtime.h>
#include <math.h>

#define NROWS 8192
#define DIM 512
#define LOGIT_SCALE 2.659f

// ---------------- device scratch (no allocations allowed) ----------------
__device__ float g_A[NROWS * DIM];   // normalized image features
__device__ float g_B[NROWS * DIM];   // normalized text features
__device__ float g_rowZ[NROWS], g_rowS[NROWS], g_colZ[NROWS], g_colS[NROWS];
__device__ float g_cntInv[NROWS];
__device__ int   g_lab[NROWS];
__device__ int   g_is64;

// ---------------- detect int64 vs int32 labels (jax x64 ambiguity) ----------------
// Examine the first 8192 int32 words (in bounds for BOTH interpretations:
// int32 case = 32KB exactly; int64 case = first half of 64KB).
// int64 little-endian: every (lo,hi) pair satisfies hi == sign_extend(lo).
// int32 labels (random 0..99) would violate this almost surely.
__global__ void k_detect(const int* __restrict__ w) {
    int ok = 1;
    for (int p = threadIdx.x; p < 4096; p += blockDim.x) {
        int lo = w[2 * p], hi = w[2 * p + 1];
        if (hi != (lo >> 31)) ok = 0;
    }
    ok = __syncthreads_and(ok);
    if (threadIdx.x == 0) g_is64 = ok;
}

// ---------------- init: decode labels, zero accumulators ----------------
__global__ void k_init(const void* __restrict__ labels) {
    int i = blockIdx.x * 256 + threadIdx.x;
    if (i >= NROWS) return;
    int lab;
    if (g_is64) lab = (int)((const long long*)labels)[i];
    else        lab = ((const int*)labels)[i];
    g_lab[i] = lab;
    g_rowZ[i] = 0.f; g_rowS[i] = 0.f;
    g_colZ[i] = 0.f; g_colS[i] = 0.f;
}

// ---------------- L2 normalize both feature matrices ----------------
// grid = 2*NROWS blocks of 128 threads; one block per row.
__global__ void k_norm(const float* __restrict__ img, const float* __restrict__ txt) {
    int b = blockIdx.x;
    const float* src; float* dst; int row;
    if (b < NROWS) { src = img; dst = g_A; row = b; }
    else           { src = txt; dst = g_B; row = b - NROWS; }
    float4 v = ((const float4*)(src + (size_t)row * DIM))[threadIdx.x];
    float ss = v.x * v.x + v.y * v.y + v.z * v.z + v.w * v.w;
#pragma unroll
    for (int m = 16; m; m >>= 1) ss += __shfl_xor_sync(0xffffffffu, ss, m);
    __shared__ float ws[4];
    if ((threadIdx.x & 31) == 0) ws[threadIdx.x >> 5] = ss;
    __syncthreads();
    float tot = ws[0] + ws[1] + ws[2] + ws[3];
    float inv = rsqrtf(fmaxf(tot, 1e-24f));  // matches max(||x||,1e-12) guard
    v.x *= inv; v.y *= inv; v.z *= inv; v.w *= inv;
    ((float4*)(dst + (size_t)row * DIM))[threadIdx.x] = v;
}

// ---------------- per-row target count: cnt_i = sum_j T_ij ----------------
__global__ void k_cnt() {
    __shared__ int slab[NROWS];
    for (int j = threadIdx.x; j < NROWS; j += 256) slab[j] = g_lab[j];
    __syncthreads();
    int i = blockIdx.x * 256 + threadIdx.x;
    int my = g_lab[i];
    float cnt;
    if (my == -1) {
        cnt = 1.f;  // only the diagonal entry
    } else {
        int c = 0;
#pragma unroll 8
        for (int j = 0; j < NROWS; j++) c += (slab[j] == my);
        cnt = (float)c;  // includes j == i
    }
    g_cntInv[i] = 1.f / cnt;
}

// ---------------- fused GEMM + exp + target-weighted accumulation ----------------
// 128x128 block tile, BK=16, 256 threads, 8x8 microtile per thread.
// Produces rowZ/rowS (shuffle-reduced across tx, global atomics) and
// colZ/colS (smem-reduced across ty, then global atomics). Logit matrix
// is never stored.
__global__ __launch_bounds__(256, 2) void k_gemm() {
    __shared__ float As[16][132];
    __shared__ float Bs[16][132];
    __shared__ int   labR[128], labC[128];
    __shared__ float cZs[128], cSs[128];

    int tid = threadIdx.x;
    int tx = tid & 15, ty = tid >> 4;
    int i0 = blockIdx.y * 128, j0 = blockIdx.x * 128;

    if (tid < 128) {
        labR[tid] = g_lab[i0 + tid];
        labC[tid] = g_lab[j0 + tid];
        cZs[tid] = 0.f; cSs[tid] = 0.f;
    }

    float acc[8][8];
#pragma unroll
    for (int r = 0; r < 8; r++)
#pragma unroll
        for (int c = 0; c < 8; c++) acc[r][c] = 0.f;

    int lrow = tid >> 2;        // 0..63
    int lseg = (tid & 3) * 4;   // 0,4,8,12

    for (int kk = 0; kk < DIM; kk += 16) {
        __syncthreads();
#pragma unroll
        for (int h = 0; h < 2; h++) {
            int row = lrow + h * 64;
            float4 a = *(const float4*)&g_A[(size_t)(i0 + row) * DIM + kk + lseg];
            As[lseg + 0][row] = a.x; As[lseg + 1][row] = a.y;
            As[lseg + 2][row] = a.z; As[lseg + 3][row] = a.w;
            float4 b = *(const float4*)&g_B[(size_t)(j0 + row) * DIM + kk + lseg];
            Bs[lseg + 0][row] = b.x; Bs[lseg + 1][row] = b.y;
            Bs[lseg + 2][row] = b.z; Bs[lseg + 3][row] = b.w;
        }
        __syncthreads();
#pragma unroll
        for (int k = 0; k < 16; k++) {
            float a[8], b[8];
            *(float4*)&a[0] = *(const float4*)&As[k][ty * 8];
            *(float4*)&a[4] = *(const float4*)&As[k][ty * 8 + 4];
            *(float4*)&b[0] = *(const float4*)&Bs[k][tx * 8];
            *(float4*)&b[4] = *(const float4*)&Bs[k][tx * 8 + 4];
#pragma unroll
            for (int r = 0; r < 8; r++)
#pragma unroll
                for (int c = 0; c < 8; c++)
                    acc[r][c] = fmaf(a[r], b[c], acc[r][c]);
        }
    }
    __syncthreads();

    // ---- epilogue: logits -> exp + target-weighted sums ----
    int lc[8];
#pragma unroll
    for (int c = 0; c < 8; c++) lc[c] = labC[tx * 8 + c];

    float rZ[8], rS[8], cZ[8], cS[8];
#pragma unroll
    for (int r = 0; r < 8; r++) { rZ[r] = 0.f; rS[r] = 0.f; cZ[r] = 0.f; cS[r] = 0.f; }

#pragma unroll
    for (int r = 0; r < 8; r++) {
        int gi = i0 + ty * 8 + r;
        int li = labR[ty * 8 + r];
        bool lv = (li != -1);
#pragma unroll
        for (int c = 0; c < 8; c++) {
            int gj = j0 + tx * 8 + c;
            float s = LOGIT_SCALE * acc[r][c];
            float e = __expf(s);
            rZ[r] += e; cZ[c] += e;
            bool t = (gi == gj) || (lv && (li == lc[c]));
            if (t) { rS[r] += s; cS[c] += s; }
        }
    }

    // rows: reduce across tx (lanes 0..15 within half-warp share ty)
#pragma unroll
    for (int m = 8; m; m >>= 1) {
#pragma unroll
        for (int r = 0; r < 8; r++) {
            rZ[r] += __shfl_xor_sync(0xffffffffu, rZ[r], m);
            rS[r] += __shfl_xor_sync(0xffffffffu, rS[r], m);
        }
    }
    if (tx == 0) {
#pragma unroll
        for (int r = 0; r < 8; r++) {
            atomicAdd(&g_rowZ[i0 + ty * 8 + r], rZ[r]);
            atomicAdd(&g_rowS[i0 + ty * 8 + r], rS[r]);
        }
    }

    // cols: combine the two ty's inside each warp (xor 16 keeps same tx),
    // then smem atomics across the 8 warps, then 128 global atomics.
#pragma unroll
    for (int c = 0; c < 8; c++) {
        cZ[c] += __shfl_xor_sync(0xffffffffu, cZ[c], 16);
        cS[c] += __shfl_xor_sync(0xffffffffu, cS[c], 16);
    }
    if ((ty & 1) == 0) {
#pragma unroll
        for (int c = 0; c < 8; c++) {
            atomicAdd(&cZs[tx * 8 + c], cZ[c]);
            atomicAdd(&cSs[tx * 8 + c], cS[c]);
        }
    }
    __syncthreads();
    if (tid < 128) {
        atomicAdd(&g_colZ[j0 + tid], cZs[tid]);
        atomicAdd(&g_colS[j0 + tid], cSs[tid]);
    }
}

// ---------------- final reduction: mean loss ----------------
__global__ void k_final(float* __restrict__ out) {
    int tid = threadIdx.x;
    float sum = 0.f;
    for (int i = tid; i < NROWS; i += 1024) {
        float inv = g_cntInv[i];
        sum += logf(g_rowZ[i]) + logf(g_colZ[i]) - (g_rowS[i] + g_colS[i]) * inv;
    }
#pragma unroll
    for (int m = 16; m; m >>= 1) sum += __shfl_xor_sync(0xffffffffu, sum, m);
    __shared__ float ws[32];
    if ((tid & 31) == 0) ws[tid >> 5] = sum;
    __syncthreads();
    if (tid < 32) {
        float v = ws[tid];
#pragma unroll
        for (int m = 16; m; m >>= 1) v += __shfl_xor_sync(0xffffffffu, v, m);
        if (tid == 0) out[0] = v / (2.0f * NROWS);
    }
}

// ---------------- launch ----------------
extern "C" void kernel_launch(void* const* d_in, const int* in_sizes, int n_in,
                              void* d_out, int out_size) {
    const float* txt = (const float*)d_in[0];  // text_features
    const float* img = (const float*)d_in[1];  // image_features
    const void*  lab = d_in[2];                // labels (int64 or int32, detected)

    k_detect<<<1, 256>>>((const int*)lab);
    k_init<<<(NROWS + 255) / 256, 256>>>(lab);
    k_norm<<<2 * NROWS, 128>>>(img, txt);
    k_cnt<<<(NROWS + 255) / 256, 256>>>();
    dim3 grid(64, 64);
    k_gemm<<<grid, 256>>>();
    k_final<<<1, 1024>>>((float*)d_out);
}

// round 3
// speedup vs baseline: 3.8031x; 3.8031x over previous
#include <cuda_runtime.h>
#include <cuda_bf16.h>
#include <math.h>
#include <stdint.h>

#define NROWS 8192
#define DIM 512
#define LOGIT_SCALE 2.659f

// ---------------- device scratch ----------------
__device__ __nv_bfloat16 g_Abf[NROWS * DIM];   // normalized image features (bf16)
__device__ __nv_bfloat16 g_Bbf[NROWS * DIM];   // normalized text features (bf16)
__device__ float g_rowZ[NROWS], g_rowS[NROWS], g_colZ[NROWS], g_colS[NROWS];
__device__ float g_cntInv[NROWS];
__device__ int   g_lab[NROWS];
__device__ int   g_hist[1024];
__device__ int   g_is64;

// ---------------- fast exp on the FMA pipe (|x| <= ~3, rel err ~2e-6) ----------------
__device__ __forceinline__ float fexp(float s) {
    float t = s * 1.4426950408889634f;          // s * log2(e), |t| <= 3.84
    float z = t + 12582912.0f;                  // round-to-nearest-int via magic number
    int   n = __float_as_int(z) - 0x4B400000;   // integer part
    float nf = z - 12582912.0f;
    float f = t - nf;                           // frac in [-0.5, 0.5]
    float p = 1.3333558146e-3f;                 // 2^f Taylor (ln2^k / k!)
    p = fmaf(p, f, 9.6181291076e-3f);
    p = fmaf(p, f, 5.5504108665e-2f);
    p = fmaf(p, f, 2.4022650696e-1f);
    p = fmaf(p, f, 6.9314718056e-1f);
    p = fmaf(p, f, 1.0f);
    return __int_as_float(__float_as_int(p) + (n << 23));  // p * 2^n
}

// ---------------- async copy helpers ----------------
#define CP_ASYNC16(dst, src) \
    asm volatile("cp.async.cg.shared.global [%0], [%1], 16;" :: "r"(dst), "l"(src))
#define CP_COMMIT() asm volatile("cp.async.commit_group;" ::: "memory")
#define CP_WAIT(n)  asm volatile("cp.async.wait_group %0;" :: "n"(n) : "memory")

__device__ __forceinline__ uint32_t smem_u32(const void* p) {
    uint32_t a;
    asm("{ .reg .u64 t; cvta.to.shared.u64 t, %1; cvt.u32.u64 %0, t; }" : "=r"(a) : "l"(p));
    return a;
}

__device__ __forceinline__ void ldmatrix_x4(uint32_t& r0, uint32_t& r1, uint32_t& r2,
                                            uint32_t& r3, uint32_t addr) {
    asm volatile("ldmatrix.sync.aligned.m8n8.x4.shared.b16 {%0,%1,%2,%3}, [%4];"
                 : "=r"(r0), "=r"(r1), "=r"(r2), "=r"(r3) : "r"(addr));
}

__device__ __forceinline__ void mma_16816(float* d, const uint32_t* a, const uint32_t* b) {
    asm volatile(
        "mma.sync.aligned.m16n8k16.row.col.f32.bf16.bf16.f32 "
        "{%0,%1,%2,%3}, {%4,%5,%6,%7}, {%8,%9}, {%0,%1,%2,%3};"
        : "+f"(d[0]), "+f"(d[1]), "+f"(d[2]), "+f"(d[3])
        : "r"(a[0]), "r"(a[1]), "r"(a[2]), "r"(a[3]), "r"(b[0]), "r"(b[1]));
}

// ---------------- label dtype detect (int64 vs int32) ----------------
__global__ void k_detect(const int* __restrict__ w) {
    int ok = 1;
    for (int p = threadIdx.x; p < 4096; p += blockDim.x) {
        int lo = w[2 * p], hi = w[2 * p + 1];
        if (hi != (lo >> 31)) ok = 0;
    }
    ok = __syncthreads_and(ok);
    if (threadIdx.x == 0) g_is64 = ok;
}

// ---------------- init ----------------
__global__ void k_init(const void* __restrict__ labels) {
    int i = blockIdx.x * 256 + threadIdx.x;
    if (i < 1024) g_hist[i] = 0;
    if (i >= NROWS) return;
    int lab = g_is64 ? (int)((const long long*)labels)[i] : ((const int*)labels)[i];
    g_lab[i] = lab;
    g_rowZ[i] = 0.f; g_rowS[i] = 0.f;
    g_colZ[i] = 0.f; g_colS[i] = 0.f;
}

__global__ void k_hist() {
    int i = blockIdx.x * 256 + threadIdx.x;
    int l = g_lab[i];
    if (l >= 0) atomicAdd(&g_hist[l & 1023], 1);
}

__global__ void k_cnt() {
    int i = blockIdx.x * 256 + threadIdx.x;
    int l = g_lab[i];
    g_cntInv[i] = (l < 0) ? 1.f : 1.f / (float)g_hist[l & 1023];
}

// ---------------- normalize + cast to bf16 ----------------
__global__ void k_norm(const float* __restrict__ img, const float* __restrict__ txt) {
    int b = blockIdx.x;
    const float* src; __nv_bfloat16* dst; int row;
    if (b < NROWS) { src = img; dst = g_Abf; row = b; }
    else           { src = txt; dst = g_Bbf; row = b - NROWS; }
    float4 v = ((const float4*)(src + (size_t)row * DIM))[threadIdx.x];
    float ss = v.x * v.x + v.y * v.y + v.z * v.z + v.w * v.w;
#pragma unroll
    for (int m = 16; m; m >>= 1) ss += __shfl_xor_sync(0xffffffffu, ss, m);
    __shared__ float ws[4];
    if ((threadIdx.x & 31) == 0) ws[threadIdx.x >> 5] = ss;
    __syncthreads();
    float inv = rsqrtf(fmaxf(ws[0] + ws[1] + ws[2] + ws[3], 1e-24f));
    __nv_bfloat162 p0 = __float22bfloat162_rn(make_float2(v.x * inv, v.y * inv));
    __nv_bfloat162 p1 = __float22bfloat162_rn(make_float2(v.z * inv, v.w * inv));
    uint2 o;
    o.x = *(uint32_t*)&p0;
    o.y = *(uint32_t*)&p1;
    *(uint2*)(dst + (size_t)row * DIM + threadIdx.x * 4) = o;
}

// ---------------- fused bf16 mma.sync GEMM + softmax-stat epilogue ----------------
// CTA tile 128x128, BK=32, 2-stage cp.async pipeline.
// Smem per stage: A 128x32 bf16 (8KB) + B 128x32 bf16 (8KB), stored as
// contiguous 8x8-tile blocks (128B each) so ldmatrix.x4 is conflict-free:
//   tile index t = (row>>3)*4 + (k>>3), elem offset (row&7)*16.
// Warp grid 4(m) x 2(n): warp tile 32x64. Per warp: 2 m16-frags x 8 n8-frags.
#define STAGE_BYTES 16384

__global__ __launch_bounds__(256, 2) void k_gemm() {
    __shared__ char smem[2 * STAGE_BYTES];
    const uint32_t sbase = smem_u32(smem);
    const int tid = threadIdx.x;
    const int lane = tid & 31, wid = tid >> 5;
    const int wm = wid & 3, wn = wid >> 2;
    const int i0 = blockIdx.y * 128, j0 = blockIdx.x * 128;

    // per-thread cp.async src/dst parameters
    const int ldr = tid >> 2;        // 0..63 (row base; +64 for second half)
    const int ldc = tid & 3;         // 8-col chunk

    // ldmatrix offsets within a stage
    const int g = lane >> 3;         // lane group 0..3
    const int lr = lane & 7;
    uint32_t aOff[2][2], bOff[4][2];
#pragma unroll
    for (int mt = 0; mt < 2; mt++)
#pragma unroll
        for (int ks = 0; ks < 2; ks++)
            aOff[mt][ks] = (uint32_t)(((wm * 4 + mt * 2 + (g & 1)) * 4 +
                                       (ks * 2 + (g >> 1))) * 128 + lr * 16);
#pragma unroll
    for (int np = 0; np < 4; np++)
#pragma unroll
        for (int ks = 0; ks < 2; ks++)
            bOff[np][ks] = (uint32_t)(8192 + ((wn * 8 + np * 2 + (g >> 1)) * 4 +
                                              (ks * 2 + (g & 1))) * 128 + lr * 16);

    float acc[2][8][4];
#pragma unroll
    for (int mt = 0; mt < 2; mt++)
#pragma unroll
        for (int nt = 0; nt < 8; nt++)
#pragma unroll
            for (int e = 0; e < 4; e++) acc[mt][nt][e] = 0.f;

    // ---- stage loader ----
    auto load_stage = [&](int s, int kk) {
        uint32_t sA = sbase + s * STAGE_BYTES;
        uint32_t sB = sA + 8192;
#pragma unroll
        for (int h = 0; h < 2; h++) {
            int r = ldr + h * 64;
            uint32_t doff = (uint32_t)(((r >> 3) * 4 + ldc) * 128 + (r & 7) * 16);
            CP_ASYNC16(sA + doff, g_Abf + (size_t)(i0 + r) * DIM + kk + ldc * 8);
            CP_ASYNC16(sB + doff, g_Bbf + (size_t)(j0 + r) * DIM + kk + ldc * 8);
        }
    };

    load_stage(0, 0);
    CP_COMMIT();

    for (int it = 0; it < 16; it++) {
        int s = it & 1;
        if (it + 1 < 16) {
            load_stage(s ^ 1, (it + 1) * 32);
            CP_COMMIT();
            CP_WAIT(1);
        } else {
            CP_WAIT(0);
        }
        __syncthreads();
        uint32_t stg = sbase + s * STAGE_BYTES;
#pragma unroll
        for (int ks = 0; ks < 2; ks++) {
            uint32_t A[2][4];
#pragma unroll
            for (int mt = 0; mt < 2; mt++)
                ldmatrix_x4(A[mt][0], A[mt][1], A[mt][2], A[mt][3], stg + aOff[mt][ks]);
            uint32_t B[8][2];
#pragma unroll
            for (int np = 0; np < 4; np++) {
                uint32_t b0, b1, b2, b3;
                ldmatrix_x4(b0, b1, b2, b3, stg + bOff[np][ks]);
                B[np * 2][0] = b0; B[np * 2][1] = b1;
                B[np * 2 + 1][0] = b2; B[np * 2 + 1][1] = b3;
            }
#pragma unroll
            for (int mt = 0; mt < 2; mt++)
#pragma unroll
                for (int nt = 0; nt < 8; nt++)
                    mma_16816(acc[mt][nt], A[mt], B[nt]);
        }
        __syncthreads();
    }

    // ---- epilogue: logits -> exp + target-weighted stats ----
    const int r_base = i0 + wm * 32 + (lane >> 2);       // +mt*16 +hb*8
    const int c_base = j0 + wn * 64 + 2 * (lane & 3);    // +nt*8 +d

    int labR[4];
#pragma unroll
    for (int q = 0; q < 4; q++) labR[q] = g_lab[r_base + (q >> 1) * 16 + (q & 1) * 8];
    int labC[16];
#pragma unroll
    for (int nt = 0; nt < 8; nt++) {
        labC[nt * 2]     = g_lab[c_base + nt * 8];
        labC[nt * 2 + 1] = g_lab[c_base + nt * 8 + 1];
    }

    float rZ[4] = {0.f, 0.f, 0.f, 0.f}, rS[4] = {0.f, 0.f, 0.f, 0.f};
    float cZ[16], cS[16];
#pragma unroll
    for (int q = 0; q < 16; q++) { cZ[q] = 0.f; cS[q] = 0.f; }

#pragma unroll
    for (int mt = 0; mt < 2; mt++)
#pragma unroll
        for (int nt = 0; nt < 8; nt++)
#pragma unroll
            for (int e = 0; e < 4; e++) {
                int hb = e >> 1, d = e & 1;
                float sv = LOGIT_SCALE * acc[mt][nt][e];
                float ex = fexp(sv);
                int gi = r_base + mt * 16 + hb * 8;
                int gj = c_base + nt * 8 + d;
                int li = labR[mt * 2 + hb];
                bool tg = (gi == gj) || (li >= 0 && li == labC[nt * 2 + d]);
                float ms = tg ? sv : 0.f;
                rZ[mt * 2 + hb] += ex; rS[mt * 2 + hb] += ms;
                cZ[nt * 2 + d] += ex;  cS[nt * 2 + d] += ms;
            }

    // rows: reduce across the 4 lanes of each quad (same lane>>2)
#pragma unroll
    for (int m = 1; m <= 2; m <<= 1)
#pragma unroll
        for (int q = 0; q < 4; q++) {
            rZ[q] += __shfl_xor_sync(0xffffffffu, rZ[q], m);
            rS[q] += __shfl_xor_sync(0xffffffffu, rS[q], m);
        }
    if ((lane & 3) == 0) {
#pragma unroll
        for (int q = 0; q < 4; q++) {
            int gi = r_base + (q >> 1) * 16 + (q & 1) * 8;
            atomicAdd(&g_rowZ[gi], rZ[q]);
            atomicAdd(&g_rowS[gi], rS[q]);
        }
    }

    // cols: reduce across lane>>2 (same lane&3)
#pragma unroll
    for (int m = 4; m <= 16; m <<= 1)
#pragma unroll
        for (int q = 0; q < 16; q++) {
            cZ[q] += __shfl_xor_sync(0xffffffffu, cZ[q], m);
            cS[q] += __shfl_xor_sync(0xffffffffu, cS[q], m);
        }
    if (lane < 4) {
#pragma unroll
        for (int q = 0; q < 16; q++) {
            int gj = j0 + wn * 64 + (q >> 1) * 8 + 2 * lane + (q & 1);
            atomicAdd(&g_colZ[gj], cZ[q]);
            atomicAdd(&g_colS[gj], cS[q]);
        }
    }
}

// ---------------- final reduction ----------------
__global__ void k_final(float* __restrict__ out) {
    int tid = threadIdx.x;
    float sum = 0.f;
    for (int i = tid; i < NROWS; i += 1024) {
        float inv = g_cntInv[i];
        sum += logf(g_rowZ[i]) + logf(g_colZ[i]) - (g_rowS[i] + g_colS[i]) * inv;
    }
#pragma unroll
    for (int m = 16; m; m >>= 1) sum += __shfl_xor_sync(0xffffffffu, sum, m);
    __shared__ float ws[32];
    if ((tid & 31) == 0) ws[tid >> 5] = sum;
    __syncthreads();
    if (tid < 32) {
        float v = ws[tid];
#pragma unroll
        for (int m = 16; m; m >>= 1) v += __shfl_xor_sync(0xffffffffu, v, m);
        if (tid == 0) out[0] = v / (2.0f * NROWS);
    }
}

// ---------------- launch ----------------
extern "C" void kernel_launch(void* const* d_in, const int* in_sizes, int n_in,
                              void* d_out, int out_size) {
    const float* txt = (const float*)d_in[0];
    const float* img = (const float*)d_in[1];
    const void*  lab = d_in[2];

    k_detect<<<1, 256>>>((const int*)lab);
    k_init<<<32, 256>>>(lab);
    k_hist<<<32, 256>>>();
    k_cnt<<<32, 256>>>();
    k_norm<<<2 * NROWS, 128>>>(img, txt);
    dim3 grid(64, 64);
    k_gemm<<<grid, 256>>>();
    k_final<<<1, 1024>>>((float*)d_out);
}